// round 10
// baseline (speedup 1.0000x reference)
#include <cuda_runtime.h>
#include <math.h>
#include <float.h>

#define B 32
#define Q 1000
#define G 64
#define HT 512
#define NW (HT / 32)
#define FR_CAP 256
#define FULLM 0xffffffffu

__device__ double g_part[B * 3];   // per-batch {cls, bbox, giou}
__device__ int    g_done = 0;

// precise giou for the loss (matches reference math)
__device__ __forceinline__ float giou_ok(float ax1, float ay1, float ax2, float ay2,
                                         float bx1, float by1, float bx2, float by2) {
    float ix1 = fmaxf(ax1, bx1), iy1 = fmaxf(ay1, by1);
    float ix2 = fminf(ax2, bx2), iy2 = fminf(ay2, by2);
    float inter  = fmaxf(ix2 - ix1, 0.f) * fmaxf(iy2 - iy1, 0.f);
    float area_a = fmaxf(ax2 - ax1, 0.f) * fmaxf(ay2 - ay1, 0.f);
    float area_b = fmaxf(bx2 - bx1, 0.f) * fmaxf(by2 - by1, 0.f);
    float uni = area_a + area_b - inter + 1e-6f;
    float iou = inter / uni;
    float ex1 = fminf(ax1, bx1), ey1 = fminf(ay1, by1);
    float ex2 = fmaxf(ax2, bx2), ey2 = fmaxf(ay2, by2);
    float enc = fmaxf(fmaxf(ex2 - ex1, 0.f) * fmaxf(ey2 - ey1, 0.f), 1e-6f);
    return iou - (enc - uni) / enc;
}

// ---------------------------------------------------------------------------
__global__ void __launch_bounds__(HT, 1) match_kernel(
        const float* __restrict__ pb, const float* __restrict__ pl,
        const float* __restrict__ gb, float* __restrict__ out) {
    const int b = blockIdx.x;
    const int tid = threadIdx.x;
    const int lane = tid & 31, wid = tid >> 5;
    const float FINF = FLT_MAX;

    __shared__ float4 pbox4[Q];     // pred box (x1,y1,x2,y2)
    __shared__ float4 aux[Q];       // (v, spc, base=-prob0, area_p)
    __shared__ float4 gt4s[G];
    __shared__ float  garea[G];
    __shared__ float  u_sh[G];
    __shared__ short  path[Q];
    __shared__ short  row4col[Q];
    __shared__ short  col4row[G];
    __shared__ unsigned char used[Q];
    __shared__ float  umin[G];
    __shared__ int    uarg[G];
    __shared__ short  freerows[FR_CAP];
    __shared__ float  red_m1[2][NW], red_m2[2][NW];
    __shared__ int    red_j1[2][NW], red_j2[2][NW];
    __shared__ double wsum[NW][3];
    __shared__ int    nfree_sh;

    // ---- load inputs, init state ----
    for (int j = tid; j < Q; j += HT) {
        float4 p = *reinterpret_cast<const float4*>(pb + ((size_t)b * Q + j) * 4);
        pbox4[j] = p;
        float l0 = pl[((size_t)b * Q + j) * 2 + 0];
        float l1 = pl[((size_t)b * Q + j) * 2 + 1];
        float base = -1.0f / (1.0f + __expf(l1 - l0));   // -softmax[0]
        float ap = fmaxf(p.z - p.x, 0.f) * fmaxf(p.w - p.y, 0.f);
        aux[j] = make_float4(0.f, FINF, base, ap);       // v=0, spc=INF
        row4col[j] = -1; used[j] = 0;
    }
    if (tid < G) {
        float4 g = *reinterpret_cast<const float4*>(gb + ((size_t)b * G + tid) * 4);
        gt4s[tid] = g;
        garea[tid] = fmaxf(g.z - g.x, 0.f) * fmaxf(g.w - g.y, 0.f);
    }
    __syncthreads();

    // cost(i,j) = base[j] + 5*L1 - 2*giou  — EXACT reference clip structure:
    // inter, area_a, area_b, and BOTH enclosing extents are clipped at 0.
    auto costf = [&](float4 p, float4 ax, float gx1, float gy1, float gx2,
                     float gy2, float ga) -> float {
        float ix1 = fmaxf(p.x, gx1), iy1 = fmaxf(p.y, gy1);
        float ix2 = fminf(p.z, gx2), iy2 = fminf(p.w, gy2);
        float inter = fmaxf(ix2 - ix1, 0.f) * fmaxf(iy2 - iy1, 0.f);
        float uni = ax.w + ga - inter + 1e-6f;
        float ex1 = fminf(p.x, gx1), ey1 = fminf(p.y, gy1);
        float ex2 = fmaxf(p.z, gx2), ey2 = fmaxf(p.w, gy2);
        float enc = fmaxf(fmaxf(ex2 - ex1, 0.f) * fmaxf(ey2 - ey1, 0.f), 1e-6f);
        float gi = __fdividef(inter, uni) - __fdividef(enc - uni, enc);
        float l1c = fabsf(p.x - gx1) + fabsf(p.y - gy1) +
                    fabsf(p.z - gx2) + fabsf(p.w - gy2);
        return fmaf(-2.f, gi, fmaf(5.f, l1c, ax.z));
    };

    // ---- P1: row minima, warp-per-row ----
    for (int r = wid; r < G; r += NW) {
        float4 g = gt4s[r]; float ga = garea[r];
        float best = FINF; int bj = Q;
        for (int j = lane; j < Q; j += 32) {
            float c = costf(pbox4[j], aux[j], g.x, g.y, g.z, g.w, ga);
            if (c < best) { best = c; bj = j; }
        }
#pragma unroll
        for (int off = 16; off > 0; off >>= 1) {
            float om = __shfl_down_sync(FULLM, best, off);
            int   oj = __shfl_down_sync(FULLM, bj, off);
            if (om < best || (om == best && oj < bj)) { best = om; bj = oj; }
        }
        if (lane == 0) { umin[r] = best; uarg[r] = bj; }
    }
    __syncthreads();
    if (tid < G) u_sh[tid] = umin[tid];
    // ---- P2: greedy tight-edge assignment ----
    if (tid == 0) {
        int nf = 0;
        for (int r = 0; r < G; r++) {
            int j = uarg[r];
            if (row4col[j] < 0) { row4col[j] = (short)r; col4row[r] = (short)j; }
            else { col4row[r] = -1; freerows[nf++] = (short)r; }
        }
        nfree_sh = nf;
    }
    __syncthreads();

    // ---- P3: augmenting row reduction, HT-wide ----
    {
        int idx = 0, cnt = nfree_sh, iters = 0, par = 0;
        while (idx < cnt && iters < 192) {
            iters++;
            int i = freerows[idx]; idx++;
            float4 g = gt4s[i]; float ga = garea[i];
            float m1 = FINF, m2 = FINF; int j1 = Q, j2 = Q;
            for (int j = tid; j < Q; j += HT) {
                float red = costf(pbox4[j], aux[j], g.x, g.y, g.z, g.w, ga) - aux[j].x;
                if (red < m1)      { m2 = m1; j2 = j1; m1 = red; j1 = j; }
                else if (red < m2) { m2 = red; j2 = j; }
            }
#pragma unroll
            for (int off = 16; off > 0; off >>= 1) {
                float b1 = __shfl_xor_sync(FULLM, m1, off);
                int  bj1 = __shfl_xor_sync(FULLM, j1, off);
                float b2 = __shfl_xor_sync(FULLM, m2, off);
                int  bj2 = __shfl_xor_sync(FULLM, j2, off);
                if (b1 < m1 || (b1 == m1 && bj1 < j1)) {
                    if (m1 < b2 || (m1 == b2 && j1 < bj2)) { m2 = m1; j2 = j1; }
                    else { m2 = b2; j2 = bj2; }
                    m1 = b1; j1 = bj1;
                } else {
                    if (b1 < m2 || (b1 == m2 && bj1 < j2)) { m2 = b1; j2 = bj1; }
                }
            }
            if (lane == 0) {
                red_m1[par][wid] = m1; red_j1[par][wid] = j1;
                red_m2[par][wid] = m2; red_j2[par][wid] = j2;
            }
            __syncthreads();
            // register-tree combine of NW slots (identical on all threads)
            {
                float a1[NW], a2[NW]; int c1[NW], c2[NW];
#pragma unroll
                for (int k = 0; k < NW; k++) {
                    a1[k] = red_m1[par][k]; c1[k] = red_j1[par][k];
                    a2[k] = red_m2[par][k]; c2[k] = red_j2[par][k];
                }
#pragma unroll
                for (int s = NW / 2; s > 0; s >>= 1) {
#pragma unroll
                    for (int k = 0; k < NW / 2; k++) {
                        if (k < s) {
                            float b1 = a1[k + s]; int bj1 = c1[k + s];
                            float b2 = a2[k + s]; int bj2 = c2[k + s];
                            if (b1 < a1[k] || (b1 == a1[k] && bj1 < c1[k])) {
                                if (a1[k] < b2 || (a1[k] == b2 && c1[k] < bj2)) { a2[k] = a1[k]; c2[k] = c1[k]; }
                                else { a2[k] = b2; c2[k] = bj2; }
                                a1[k] = b1; c1[k] = bj1;
                            } else {
                                if (b1 < a2[k] || (b1 == a2[k] && bj1 < c2[k])) { a2[k] = b1; c2[k] = bj1; }
                            }
                        }
                    }
                }
                m1 = a1[0]; j1 = c1[0]; m2 = a2[0]; j2 = c2[0];
            }
            // decision (ALL threads read row4col BEFORE tid0 writes it)
            bool strict = (m1 < m2);
            int jt = j1;
            int i0 = row4col[jt];
            if (!strict && i0 >= 0 && j2 < Q) { jt = j2; i0 = row4col[jt]; }
            __syncthreads();   // order decision-reads before tid0's writes
            if (i0 >= 0) {
                if (strict) idx--;
                else if (cnt < FR_CAP) cnt++;
            }
            if (tid == 0) {
                u_sh[i] = m2;
                if (strict) aux[jt].x -= (m2 - m1);
                row4col[jt] = (short)i; col4row[i] = (short)jt;
                if (i0 >= 0) {
                    col4row[i0] = -1;
                    if (strict) freerows[idx] = (short)i0;
                    else if (cnt - 1 < FR_CAP) freerows[cnt - 1] = (short)i0;
                }
            }
            par ^= 1;
            __syncthreads();
        }
    }

    // ---- P4: SAP (HT-wide, owner-private spc/used) ----
    for (int cur = 0; cur < G; cur++) {
        if (col4row[cur] >= 0) continue;

        int i = cur, par = 0, sink = -1;
        float minVal = 0.f;

        while (true) {
            float muv = minVal - u_sh[i];
            float4 g = gt4s[i]; float ga = garea[i];
            float best = FINF; int bestj = 0x7FFFFFFF;
            for (int j = tid; j < Q; j += HT) {
                if (!used[j]) {
                    float4 ax = aux[j];
                    float r = muv + costf(pbox4[j], ax, g.x, g.y, g.z, g.w, ga) - ax.x;
                    float s = ax.y;
                    if (r < s) { s = r; aux[j].y = r; path[j] = (short)i; }
                    if (s < best) { best = s; bestj = j; }
                }
            }
#pragma unroll
            for (int off = 16; off > 0; off >>= 1) {
                float ob = __shfl_down_sync(FULLM, best, off);
                int   oj = __shfl_down_sync(FULLM, bestj, off);
                if (ob < best || (ob == best && oj < bestj)) { best = ob; bestj = oj; }
            }
            if (lane == 0) { red_m1[par][wid] = best; red_j1[par][wid] = bestj; }
            __syncthreads();
            {
                float a1[NW]; int c1[NW];
#pragma unroll
                for (int k = 0; k < NW; k++) { a1[k] = red_m1[par][k]; c1[k] = red_j1[par][k]; }
#pragma unroll
                for (int s = NW / 2; s > 0; s >>= 1) {
#pragma unroll
                    for (int k = 0; k < NW / 2; k++) {
                        if (k < s) {
                            float ob = a1[k + s]; int oj = c1[k + s];
                            if (ob < a1[k] || (ob == a1[k] && oj < c1[k])) { a1[k] = ob; c1[k] = oj; }
                        }
                    }
                }
                best = a1[0]; bestj = c1[0];
            }
            minVal = best;
            int j1 = bestj;
            if ((j1 & (HT - 1)) == tid) used[j1] = 1;   // owner-private flag
            par ^= 1;
            int nr = row4col[j1];     // row4col constant during pop loop: safe
            if (nr < 0) { sink = j1; break; }
            i = nr;
        }
        __syncthreads();

        // dual updates (owner-stride; distinct rows per used column -> race-free)
        for (int j = tid; j < Q; j += HT) {
            if (used[j]) {
                float d = minVal - aux[j].y;
                int r = row4col[j];
                if (r >= 0) u_sh[r] += d;
                aux[j].x -= d;
            }
        }
        __syncthreads();
        if (tid == 0) {
            u_sh[cur] += minVal;
            int j = sink;
            while (true) {
                int i2 = path[j];
                row4col[j] = (short)i2;
                int tcol = col4row[i2];
                col4row[i2] = (short)j;
                j = tcol;
                if (i2 == cur) break;
            }
        }
        // reset search state (owner-private; disjoint from tid0's arrays)
        for (int j = tid; j < Q; j += HT) { aux[j].y = FINF; used[j] = 0; }
        __syncthreads();
    }

    // ---- fused per-batch losses (fp64) ----
    double cls = 0.0, bbox = 0.0, gio = 0.0;
    for (int q = tid; q < Q; q += HT) {
        float l0 = pl[((size_t)b * Q + q) * 2 + 0];
        float l1 = pl[((size_t)b * Q + q) * 2 + 1];
        float mx = fmaxf(l0, l1);
        float lse = mx + logf(expf(l0 - mx) + expf(l1 - mx));
        cls += 0.1 * (double)(lse - l1);
    }
    if (tid < G) {
        int g = tid;
        int q = col4row[g];
        float4 mg = gt4s[g];
        float4 mp = pbox4[q];
        bbox = (double)(fabsf(mp.x - mg.x) + fabsf(mp.y - mg.y) +
                        fabsf(mp.z - mg.z) + fabsf(mp.w - mg.w));
        gio = 1.0 - (double)giou_ok(mp.x, mp.y, mp.z, mp.w, mg.x, mg.y, mg.z, mg.w);
        float l0 = pl[((size_t)b * Q + q) * 2 + 0];
        float l1 = pl[((size_t)b * Q + q) * 2 + 1];
        float mx = fmaxf(l0, l1);
        float lse = mx + logf(expf(l0 - mx) + expf(l1 - mx));
        cls += (double)(lse - l0) - 0.1 * (double)(lse - l1);
    }
#pragma unroll
    for (int off = 16; off > 0; off >>= 1) {
        cls  += __shfl_down_sync(FULLM, cls, off);
        bbox += __shfl_down_sync(FULLM, bbox, off);
        gio  += __shfl_down_sync(FULLM, gio, off);
    }
    if (lane == 0) { wsum[wid][0] = cls; wsum[wid][1] = bbox; wsum[wid][2] = gio; }
    __syncthreads();

    if (tid == 0) {
        double cls_t = 0.0, bbox_t = 0.0, gio_t = 0.0;
        for (int w = 0; w < NW; w++) {
            cls_t += wsum[w][0]; bbox_t += wsum[w][1]; gio_t += wsum[w][2];
        }
        g_part[b * 3 + 0] = cls_t;
        g_part[b * 3 + 1] = bbox_t;
        g_part[b * 3 + 2] = gio_t;
        __threadfence();
        int prev = atomicAdd(&g_done, 1);
        if (prev == B - 1) {
            g_done = 0;
            __threadfence();
            double csum = 0.0, bsum = 0.0, gsum = 0.0;
            for (int k = 0; k < B; k++) {
                csum += g_part[k * 3 + 0];
                bsum += g_part[k * 3 + 1];
                gsum += g_part[k * 3 + 2];
            }
            const double wt_sum = 64.0 + (double)(Q - G) * 0.1;  // 157.6
            double lc = (csum / wt_sum) / (double)B;
            double nb = (double)(B * G);
            double lb = bsum / nb;
            double lg = gsum / nb;
            out[0] = (float)(1.0 * lc + 5.0 * lb + 2.0 * lg);
            out[1] = (float)lc;
            out[2] = (float)lb;
            out[3] = (float)lg;
        }
    }
}

// ---------------------------------------------------------------------------
extern "C" void kernel_launch(void* const* d_in, const int* in_sizes, int n_in,
                              void* d_out, int out_size) {
    const float* pred_boxes  = (const float*)d_in[0];  // [32,1000,4]
    const float* pred_logits = (const float*)d_in[1];  // [32,1000,2]
    const float* gt_boxes    = (const float*)d_in[2];  // [32,64,4]
    float* out = (float*)d_out;

    match_kernel<<<B, HT>>>(pred_boxes, pred_logits, gt_boxes, out);
}

// round 11
// speedup vs baseline: 1.1206x; 1.1206x over previous
#include <cuda_runtime.h>
#include <math.h>
#include <float.h>

#define B 32
#define Q 1000
#define G 64
#define HT 256
#define NW (HT / 32)
#define FR_CAP 256
#define FULLM 0xffffffffu

__device__ double g_part[B * 3];   // per-batch {cls, bbox, giou}
__device__ int    g_done = 0;

// precise giou for the loss (matches reference math)
__device__ __forceinline__ float giou_ok(float ax1, float ay1, float ax2, float ay2,
                                         float bx1, float by1, float bx2, float by2) {
    float ix1 = fmaxf(ax1, bx1), iy1 = fmaxf(ay1, by1);
    float ix2 = fminf(ax2, bx2), iy2 = fminf(ay2, by2);
    float inter  = fmaxf(ix2 - ix1, 0.f) * fmaxf(iy2 - iy1, 0.f);
    float area_a = fmaxf(ax2 - ax1, 0.f) * fmaxf(ay2 - ay1, 0.f);
    float area_b = fmaxf(bx2 - bx1, 0.f) * fmaxf(by2 - by1, 0.f);
    float uni = area_a + area_b - inter + 1e-6f;
    float iou = inter / uni;
    float ex1 = fminf(ax1, bx1), ey1 = fminf(ay1, by1);
    float ex2 = fmaxf(ax2, bx2), ey2 = fmaxf(ay2, by2);
    float enc = fmaxf(fmaxf(ex2 - ex1, 0.f) * fmaxf(ey2 - ey1, 0.f), 1e-6f);
    return iou - (enc - uni) / enc;
}

// ---------------------------------------------------------------------------
__global__ void __launch_bounds__(HT, 1) match_kernel(
        const float* __restrict__ pb, const float* __restrict__ pl,
        const float* __restrict__ gb, float* __restrict__ out) {
    const int b = blockIdx.x;
    const int tid = threadIdx.x;
    const int lane = tid & 31, wid = tid >> 5;
    const float FINF = FLT_MAX;

    __shared__ float4 pbox4[Q];     // pred box (x1,y1,x2,y2)
    __shared__ float4 aux[Q];       // (v, spc, base=-prob0, area_p)
    __shared__ float4 gt4s[G];
    __shared__ float  garea[G];
    __shared__ float  u_sh[G];
    __shared__ short  path[Q];
    __shared__ short  row4col[Q];
    __shared__ short  col4row[G];
    __shared__ unsigned char used[Q];
    __shared__ float  umin[G];
    __shared__ int    uarg[G];
    __shared__ short  freerows[FR_CAP];
    __shared__ float  red_m1[2][NW], red_m2[2][NW];
    __shared__ int    red_j1[2][NW], red_j2[2][NW];
    __shared__ double wsum[NW][3];
    __shared__ int    nfree_sh;

    // ---- load inputs, init state ----
    for (int j = tid; j < Q; j += HT) {
        float4 p = *reinterpret_cast<const float4*>(pb + ((size_t)b * Q + j) * 4);
        pbox4[j] = p;
        float l0 = pl[((size_t)b * Q + j) * 2 + 0];
        float l1 = pl[((size_t)b * Q + j) * 2 + 1];
        float base = -1.0f / (1.0f + __expf(l1 - l0));   // -softmax[0]
        float ap = fmaxf(p.z - p.x, 0.f) * fmaxf(p.w - p.y, 0.f);
        aux[j] = make_float4(0.f, FINF, base, ap);       // v=0, spc=INF
        row4col[j] = -1; used[j] = 0;
    }
    if (tid < G) {
        float4 g = *reinterpret_cast<const float4*>(gb + ((size_t)b * G + tid) * 4);
        gt4s[tid] = g;
        garea[tid] = fmaxf(g.z - g.x, 0.f) * fmaxf(g.w - g.y, 0.f);
    }
    __syncthreads();

    // cost(i,j) = base[j] + 5*L1 - 2*giou  — exact reference clip structure
    auto costf = [&](float4 p, float4 ax, float gx1, float gy1, float gx2,
                     float gy2, float ga) -> float {
        float ix1 = fmaxf(p.x, gx1), iy1 = fmaxf(p.y, gy1);
        float ix2 = fminf(p.z, gx2), iy2 = fminf(p.w, gy2);
        float inter = fmaxf(ix2 - ix1, 0.f) * fmaxf(iy2 - iy1, 0.f);
        float uni = ax.w + ga - inter + 1e-6f;
        float ex1 = fminf(p.x, gx1), ey1 = fminf(p.y, gy1);
        float ex2 = fmaxf(p.z, gx2), ey2 = fmaxf(p.w, gy2);
        float enc = fmaxf(fmaxf(ex2 - ex1, 0.f) * fmaxf(ey2 - ey1, 0.f), 1e-6f);
        float gi = __fdividef(inter, uni) - __fdividef(enc - uni, enc);
        float l1c = fabsf(p.x - gx1) + fabsf(p.y - gy1) +
                    fabsf(p.z - gx2) + fabsf(p.w - gy2);
        return fmaf(-2.f, gi, fmaf(5.f, l1c, ax.z));
    };

    // ---- P1: row minima, warp-per-row ----
    for (int r = wid; r < G; r += NW) {
        float4 g = gt4s[r]; float ga = garea[r];
        float best = FINF; int bj = Q;
        for (int j = lane; j < Q; j += 32) {
            float c = costf(pbox4[j], aux[j], g.x, g.y, g.z, g.w, ga);
            if (c < best) { best = c; bj = j; }
        }
#pragma unroll
        for (int off = 16; off > 0; off >>= 1) {
            float om = __shfl_down_sync(FULLM, best, off);
            int   oj = __shfl_down_sync(FULLM, bj, off);
            if (om < best || (om == best && oj < bj)) { best = om; bj = oj; }
        }
        if (lane == 0) { umin[r] = best; uarg[r] = bj; }
    }
    __syncthreads();
    if (tid < G) u_sh[tid] = umin[tid];
    // ---- P2: greedy tight-edge assignment ----
    if (tid == 0) {
        int nf = 0;
        for (int r = 0; r < G; r++) {
            int j = uarg[r];
            if (row4col[j] < 0) { row4col[j] = (short)r; col4row[r] = (short)j; }
            else { col4row[r] = -1; freerows[nf++] = (short)r; }
        }
        nfree_sh = nf;
    }
    __syncthreads();

    // ---- P3: augmenting row reduction, HT-wide ----
    {
        int idx = 0, cnt = nfree_sh, iters = 0, par = 0;
        while (idx < cnt && iters < 192) {
            iters++;
            int i = freerows[idx]; idx++;
            float4 g = gt4s[i]; float ga = garea[i];
            float m1 = FINF, m2 = FINF; int j1 = Q, j2 = Q;
            for (int j = tid; j < Q; j += HT) {
                float red = costf(pbox4[j], aux[j], g.x, g.y, g.z, g.w, ga) - aux[j].x;
                if (red < m1)      { m2 = m1; j2 = j1; m1 = red; j1 = j; }
                else if (red < m2) { m2 = red; j2 = j; }
            }
#pragma unroll
            for (int off = 16; off > 0; off >>= 1) {
                float b1 = __shfl_xor_sync(FULLM, m1, off);
                int  bj1 = __shfl_xor_sync(FULLM, j1, off);
                float b2 = __shfl_xor_sync(FULLM, m2, off);
                int  bj2 = __shfl_xor_sync(FULLM, j2, off);
                if (b1 < m1 || (b1 == m1 && bj1 < j1)) {
                    if (m1 < b2 || (m1 == b2 && j1 < bj2)) { m2 = m1; j2 = j1; }
                    else { m2 = b2; j2 = bj2; }
                    m1 = b1; j1 = bj1;
                } else {
                    if (b1 < m2 || (b1 == m2 && bj1 < j2)) { m2 = b1; j2 = bj1; }
                }
            }
            if (lane == 0) {
                red_m1[par][wid] = m1; red_j1[par][wid] = j1;
                red_m2[par][wid] = m2; red_j2[par][wid] = j2;
            }
            __syncthreads();
            // register-tree combine of NW slots (identical on all threads)
            {
                float a1[NW], a2[NW]; int c1[NW], c2[NW];
#pragma unroll
                for (int k = 0; k < NW; k++) {
                    a1[k] = red_m1[par][k]; c1[k] = red_j1[par][k];
                    a2[k] = red_m2[par][k]; c2[k] = red_j2[par][k];
                }
#pragma unroll
                for (int s = NW / 2; s > 0; s >>= 1) {
#pragma unroll
                    for (int k = 0; k < NW / 2; k++) {
                        if (k < s) {
                            float b1 = a1[k + s]; int bj1 = c1[k + s];
                            float b2 = a2[k + s]; int bj2 = c2[k + s];
                            if (b1 < a1[k] || (b1 == a1[k] && bj1 < c1[k])) {
                                if (a1[k] < b2 || (a1[k] == b2 && c1[k] < bj2)) { a2[k] = a1[k]; c2[k] = c1[k]; }
                                else { a2[k] = b2; c2[k] = bj2; }
                                a1[k] = b1; c1[k] = bj1;
                            } else {
                                if (b1 < a2[k] || (b1 == a2[k] && bj1 < c2[k])) { a2[k] = b1; c2[k] = bj1; }
                            }
                        }
                    }
                }
                m1 = a1[0]; j1 = c1[0]; m2 = a2[0]; j2 = c2[0];
            }
            // decision (ALL threads read row4col BEFORE tid0 writes it)
            bool strict = (m1 < m2);
            int jt = j1;
            int i0 = row4col[jt];
            if (!strict && i0 >= 0 && j2 < Q) { jt = j2; i0 = row4col[jt]; }
            __syncthreads();   // order decision-reads before tid0's writes
            if (i0 >= 0) {
                if (strict) idx--;
                else if (cnt < FR_CAP) cnt++;
            }
            if (tid == 0) {
                u_sh[i] = m2;
                if (strict) aux[jt].x -= (m2 - m1);
                row4col[jt] = (short)i; col4row[i] = (short)jt;
                if (i0 >= 0) {
                    col4row[i0] = -1;
                    if (strict) freerows[idx] = (short)i0;
                    else if (cnt - 1 < FR_CAP) freerows[cnt - 1] = (short)i0;
                }
            }
            par ^= 1;
            __syncthreads();
        }
    }

    // ---- P4: SAP (HT-wide, owner-private spc/used) ----
    for (int cur = 0; cur < G; cur++) {
        if (col4row[cur] >= 0) continue;

        int i = cur, par = 0, sink = -1;
        float minVal = 0.f;

        while (true) {
            float muv = minVal - u_sh[i];
            float4 g = gt4s[i]; float ga = garea[i];
            float best = FINF; int bestj = 0x7FFFFFFF;
            for (int j = tid; j < Q; j += HT) {
                if (!used[j]) {
                    float4 ax = aux[j];
                    float r = muv + costf(pbox4[j], ax, g.x, g.y, g.z, g.w, ga) - ax.x;
                    float s = ax.y;
                    if (r < s) { s = r; aux[j].y = r; path[j] = (short)i; }
                    if (s < best) { best = s; bestj = j; }
                }
            }
#pragma unroll
            for (int off = 16; off > 0; off >>= 1) {
                float ob = __shfl_down_sync(FULLM, best, off);
                int   oj = __shfl_down_sync(FULLM, bestj, off);
                if (ob < best || (ob == best && oj < bestj)) { best = ob; bestj = oj; }
            }
            if (lane == 0) { red_m1[par][wid] = best; red_j1[par][wid] = bestj; }
            __syncthreads();
            {
                float a1[NW]; int c1[NW];
#pragma unroll
                for (int k = 0; k < NW; k++) { a1[k] = red_m1[par][k]; c1[k] = red_j1[par][k]; }
#pragma unroll
                for (int s = NW / 2; s > 0; s >>= 1) {
#pragma unroll
                    for (int k = 0; k < NW / 2; k++) {
                        if (k < s) {
                            float ob = a1[k + s]; int oj = c1[k + s];
                            if (ob < a1[k] || (ob == a1[k] && oj < c1[k])) { a1[k] = ob; c1[k] = oj; }
                        }
                    }
                }
                best = a1[0]; bestj = c1[0];
            }
            minVal = best;
            int j1 = bestj;
            if ((j1 & (HT - 1)) == tid) used[j1] = 1;   // owner-private flag
            par ^= 1;
            int nr = row4col[j1];     // row4col constant during pop loop: safe
            if (nr < 0) { sink = j1; break; }
            i = nr;
        }
        __syncthreads();

        // dual updates (owner-stride; distinct rows per used column -> race-free)
        for (int j = tid; j < Q; j += HT) {
            if (used[j]) {
                float d = minVal - aux[j].y;
                int r = row4col[j];
                if (r >= 0) u_sh[r] += d;
                aux[j].x -= d;
            }
        }
        __syncthreads();
        if (tid == 0) {
            u_sh[cur] += minVal;
            int j = sink;
            while (true) {
                int i2 = path[j];
                row4col[j] = (short)i2;
                int tcol = col4row[i2];
                col4row[i2] = (short)j;
                j = tcol;
                if (i2 == cur) break;
            }
        }
        // reset search state (owner-private; disjoint from tid0's arrays)
        for (int j = tid; j < Q; j += HT) { aux[j].y = FINF; used[j] = 0; }
        __syncthreads();
    }

    // ---- fused per-batch losses (fp64) ----
    double cls = 0.0, bbox = 0.0, gio = 0.0;
    for (int q = tid; q < Q; q += HT) {
        float l0 = pl[((size_t)b * Q + q) * 2 + 0];
        float l1 = pl[((size_t)b * Q + q) * 2 + 1];
        float mx = fmaxf(l0, l1);
        float lse = mx + logf(expf(l0 - mx) + expf(l1 - mx));
        cls += 0.1 * (double)(lse - l1);
    }
    if (tid < G) {
        int g = tid;
        int q = col4row[g];
        float4 mg = gt4s[g];
        float4 mp = pbox4[q];
        bbox = (double)(fabsf(mp.x - mg.x) + fabsf(mp.y - mg.y) +
                        fabsf(mp.z - mg.z) + fabsf(mp.w - mg.w));
        gio = 1.0 - (double)giou_ok(mp.x, mp.y, mp.z, mp.w, mg.x, mg.y, mg.z, mg.w);
        float l0 = pl[((size_t)b * Q + q) * 2 + 0];
        float l1 = pl[((size_t)b * Q + q) * 2 + 1];
        float mx = fmaxf(l0, l1);
        float lse = mx + logf(expf(l0 - mx) + expf(l1 - mx));
        cls += (double)(lse - l0) - 0.1 * (double)(lse - l1);
    }
#pragma unroll
    for (int off = 16; off > 0; off >>= 1) {
        cls  += __shfl_down_sync(FULLM, cls, off);
        bbox += __shfl_down_sync(FULLM, bbox, off);
        gio  += __shfl_down_sync(FULLM, gio, off);
    }
    if (lane == 0) { wsum[wid][0] = cls; wsum[wid][1] = bbox; wsum[wid][2] = gio; }
    __syncthreads();

    if (tid == 0) {
        double cls_t = 0.0, bbox_t = 0.0, gio_t = 0.0;
        for (int w = 0; w < NW; w++) {
            cls_t += wsum[w][0]; bbox_t += wsum[w][1]; gio_t += wsum[w][2];
        }
        g_part[b * 3 + 0] = cls_t;
        g_part[b * 3 + 1] = bbox_t;
        g_part[b * 3 + 2] = gio_t;
        __threadfence();
        int prev = atomicAdd(&g_done, 1);
        if (prev == B - 1) {
            g_done = 0;
            __threadfence();
            double csum = 0.0, bsum = 0.0, gsum = 0.0;
            for (int k = 0; k < B; k++) {
                csum += g_part[k * 3 + 0];
                bsum += g_part[k * 3 + 1];
                gsum += g_part[k * 3 + 2];
            }
            const double wt_sum = 64.0 + (double)(Q - G) * 0.1;  // 157.6
            double lc = (csum / wt_sum) / (double)B;
            double nb = (double)(B * G);
            double lb = bsum / nb;
            double lg = gsum / nb;
            out[0] = (float)(1.0 * lc + 5.0 * lb + 2.0 * lg);
            out[1] = (float)lc;
            out[2] = (float)lb;
            out[3] = (float)lg;
        }
    }
}

// ---------------------------------------------------------------------------
extern "C" void kernel_launch(void* const* d_in, const int* in_sizes, int n_in,
                              void* d_out, int out_size) {
    const float* pred_boxes  = (const float*)d_in[0];  // [32,1000,4]
    const float* pred_logits = (const float*)d_in[1];  // [32,1000,2]
    const float* gt_boxes    = (const float*)d_in[2];  // [32,64,4]
    float* out = (float*)d_out;

    match_kernel<<<B, HT>>>(pred_boxes, pred_logits, gt_boxes, out);
}

// round 12
// speedup vs baseline: 1.3205x; 1.1784x over previous
#include <cuda_runtime.h>
#include <math.h>
#include <float.h>

#define B 32
#define Q 1000
#define G 64
#define HT 256
#define NW (HT / 32)
#define FR_CAP 256
#define FULLM 0xffffffffu
#define KMAX 0xFFFFFFFFFFFFFFFFull

__device__ double g_part[B * 3];   // per-batch {cls, bbox, giou}
__device__ int    g_done = 0;

// ---- orderable (float,idx) packing: min(key) == (min value, then min idx) ----
__device__ __forceinline__ unsigned long long fkey(float f, int j) {
    unsigned u = __float_as_uint(f);
    u = (u & 0x80000000u) ? ~u : (u | 0x80000000u);
    return ((unsigned long long)u << 32) | (unsigned)j;
}
__device__ __forceinline__ float kval(unsigned long long k) {
    unsigned u = (unsigned)(k >> 32);
    u = (u & 0x80000000u) ? (u & 0x7fffffffu) : ~u;
    return __uint_as_float(u);
}
__device__ __forceinline__ int kidx(unsigned long long k) { return (int)(k & 0xffffffffu); }
__device__ __forceinline__ unsigned long long umin64(unsigned long long a, unsigned long long b) { return a < b ? a : b; }
__device__ __forceinline__ unsigned long long umax64(unsigned long long a, unsigned long long b) { return a > b ? a : b; }

// precise giou for the loss (matches reference math)
__device__ __forceinline__ float giou_ok(float ax1, float ay1, float ax2, float ay2,
                                         float bx1, float by1, float bx2, float by2) {
    float ix1 = fmaxf(ax1, bx1), iy1 = fmaxf(ay1, by1);
    float ix2 = fminf(ax2, bx2), iy2 = fminf(ay2, by2);
    float inter  = fmaxf(ix2 - ix1, 0.f) * fmaxf(iy2 - iy1, 0.f);
    float area_a = fmaxf(ax2 - ax1, 0.f) * fmaxf(ay2 - ay1, 0.f);
    float area_b = fmaxf(bx2 - bx1, 0.f) * fmaxf(by2 - by1, 0.f);
    float uni = area_a + area_b - inter + 1e-6f;
    float iou = inter / uni;
    float ex1 = fminf(ax1, bx1), ey1 = fminf(ay1, by1);
    float ex2 = fmaxf(ax2, bx2), ey2 = fmaxf(ay2, by2);
    float enc = fmaxf(fmaxf(ex2 - ex1, 0.f) * fmaxf(ey2 - ey1, 0.f), 1e-6f);
    return iou - (enc - uni) / enc;
}

// matching cost (exact reference clip structure; same float math as R10/R11)
__device__ __forceinline__ float costf(float4 p, float base, float ap,
                                       float4 g, float ga) {
    float ix1 = fmaxf(p.x, g.x), iy1 = fmaxf(p.y, g.y);
    float ix2 = fminf(p.z, g.z), iy2 = fminf(p.w, g.w);
    float inter = fmaxf(ix2 - ix1, 0.f) * fmaxf(iy2 - iy1, 0.f);
    float uni = ap + ga - inter + 1e-6f;
    float ex1 = fminf(p.x, g.x), ey1 = fminf(p.y, g.y);
    float ex2 = fmaxf(p.z, g.z), ey2 = fmaxf(p.w, g.w);
    float enc = fmaxf(fmaxf(ex2 - ex1, 0.f) * fmaxf(ey2 - ey1, 0.f), 1e-6f);
    float gi = __fdividef(inter, uni) - __fdividef(enc - uni, enc);
    float l1c = fabsf(p.x - g.x) + fabsf(p.y - g.y) +
                fabsf(p.z - g.z) + fabsf(p.w - g.w);
    return fmaf(-2.f, gi, fmaf(5.f, l1c, base));
}

// ---------------------------------------------------------------------------
__global__ void __launch_bounds__(HT, 1) match_kernel(
        const float* __restrict__ pb, const float* __restrict__ pl,
        const float* __restrict__ gb, float* __restrict__ out) {
    const int b = blockIdx.x;
    const int tid = threadIdx.x;
    const int lane = tid & 31, wid = tid >> 5;
    const float FINF = FLT_MAX;

    __shared__ float4 pbox4[Q];
    __shared__ float2 baux[Q];          // (base=-prob0, area_p) for P1 + reg load
    __shared__ float4 gt4s[G];
    __shared__ float  garea[G];
    __shared__ float  u_sh[G];
    __shared__ short  path[Q];
    __shared__ short  row4col[Q];
    __shared__ short  col4row[G];
    __shared__ float  umin[G];
    __shared__ int    uarg[G];
    __shared__ short  freerows[FR_CAP];
    __shared__ unsigned long long sl1[2][NW], sl2[2][NW];
    __shared__ double wsum[NW][3];
    __shared__ int    nfree_sh;

    // ---- load inputs ----
    for (int j = tid; j < Q; j += HT) {
        float4 p = *reinterpret_cast<const float4*>(pb + ((size_t)b * Q + j) * 4);
        pbox4[j] = p;
        float l0 = pl[((size_t)b * Q + j) * 2 + 0];
        float l1 = pl[((size_t)b * Q + j) * 2 + 1];
        float base = -1.0f / (1.0f + __expf(l1 - l0));
        float ap = fmaxf(p.z - p.x, 0.f) * fmaxf(p.w - p.y, 0.f);
        baux[j] = make_float2(base, ap);
        row4col[j] = -1;
    }
    if (tid < G) {
        float4 g = *reinterpret_cast<const float4*>(gb + ((size_t)b * G + tid) * 4);
        gt4s[tid] = g;
        garea[tid] = fmaxf(g.z - g.x, 0.f) * fmaxf(g.w - g.y, 0.f);
    }
    __syncthreads();

    // ---- register-cache this thread's 4 owned columns (j = tid + 256k) ----
    const int nk = (tid < Q - 3 * HT) ? 4 : 3;     // k=3 valid iff tid < 232
    float4 c_p[4]; float c_b[4], c_a[4], v_reg[4], spc_reg[4];
    int usedmask = 0;
#pragma unroll
    for (int k = 0; k < 4; k++) {
        int j = tid + HT * k;
        if (j < Q) {
            c_p[k] = pbox4[j];
            float2 ba = baux[j];
            c_b[k] = ba.x; c_a[k] = ba.y;
        }
        v_reg[k] = 0.f; spc_reg[k] = FINF;
    }

    // ---- P1: row minima, warp-per-row ----
    for (int r = wid; r < G; r += NW) {
        float4 g = gt4s[r]; float ga = garea[r];
        float best = FINF; int bj = Q;
        for (int j = lane; j < Q; j += 32) {
            float2 ba = baux[j];
            float c = costf(pbox4[j], ba.x, ba.y, g, ga);
            if (c < best) { best = c; bj = j; }
        }
#pragma unroll
        for (int off = 16; off > 0; off >>= 1) {
            float om = __shfl_down_sync(FULLM, best, off);
            int   oj = __shfl_down_sync(FULLM, bj, off);
            if (om < best || (om == best && oj < bj)) { best = om; bj = oj; }
        }
        if (lane == 0) { umin[r] = best; uarg[r] = bj; }
    }
    __syncthreads();
    if (tid < G) u_sh[tid] = umin[tid];
    // ---- P2: greedy tight-edge assignment ----
    if (tid == 0) {
        int nf = 0;
        for (int r = 0; r < G; r++) {
            int j = uarg[r];
            if (row4col[j] < 0) { row4col[j] = (short)r; col4row[r] = (short)j; }
            else { col4row[r] = -1; freerows[nf++] = (short)r; }
        }
        nfree_sh = nf;
    }
    __syncthreads();

    // ---- P3: augmenting row reduction (packed keys, reg v) ----
    {
        int idx = 0, cnt = nfree_sh, iters = 0, par = 0;
        while (idx < cnt && iters < 192) {
            iters++;
            int i = freerows[idx]; idx++;
            float4 g = gt4s[i]; float ga = garea[i];
            unsigned long long k1 = KMAX, k2 = KMAX;
#pragma unroll
            for (int k = 0; k < 4; k++) {
                if (k < nk) {
                    int j = tid + HT * k;
                    float red = costf(c_p[k], c_b[k], c_a[k], g, ga) - v_reg[k];
                    unsigned long long kk = fkey(red, j);
                    if (kk < k1) { k2 = k1; k1 = kk; }
                    else if (kk < k2) { k2 = kk; }
                }
            }
#pragma unroll
            for (int off = 16; off > 0; off >>= 1) {
                unsigned long long o1 = __shfl_xor_sync(FULLM, k1, off);
                unsigned long long o2 = __shfl_xor_sync(FULLM, k2, off);
                unsigned long long mx = umax64(k1, o1);
                k1 = umin64(k1, o1);
                k2 = umin64(mx, umin64(k2, o2));
            }
            if (lane == 0) { sl1[par][wid] = k1; sl2[par][wid] = k2; }
            __syncthreads();
            unsigned long long K1 = sl1[par][0], K2 = sl2[par][0];
#pragma unroll
            for (int k = 1; k < NW; k++) {
                unsigned long long o1 = sl1[par][k], o2 = sl2[par][k];
                unsigned long long mx = umax64(K1, o1);
                K1 = umin64(K1, o1);
                K2 = umin64(mx, umin64(K2, o2));
            }
            float m1 = kval(K1), m2 = kval(K2);
            int j1 = kidx(K1), j2 = kidx(K2);
            // decision (ALL threads read row4col BEFORE tid0 writes it)
            bool strict = (m1 < m2);
            int jt = j1;
            int i0 = row4col[jt];
            if (!strict && i0 >= 0 && j2 < Q) { jt = j2; i0 = row4col[jt]; }
            __syncthreads();   // order decision-reads before tid0's writes
            if (i0 >= 0) {
                if (strict) idx--;
                else if (cnt < FR_CAP) cnt++;
            }
            // v update: owner applies the (identically computed) delta
            if (strict && ((jt & (HT - 1)) == tid)) v_reg[jt >> 8] -= (m2 - m1);
            if (tid == 0) {
                u_sh[i] = m2;
                row4col[jt] = (short)i; col4row[i] = (short)jt;
                if (i0 >= 0) {
                    col4row[i0] = -1;
                    if (strict) freerows[idx] = (short)i0;
                    else if (cnt - 1 < FR_CAP) freerows[cnt - 1] = (short)i0;
                }
            }
            par ^= 1;
            __syncthreads();
        }
    }

    // ---- P4: SAP (reg spc/used/v; one barrier per pop) ----
    for (int cur = 0; cur < G; cur++) {
        if (col4row[cur] >= 0) continue;

        int i = cur, par = 0, sink = -1;
        float minVal = 0.f;

        while (true) {
            float muv = minVal - u_sh[i];
            float4 g = gt4s[i]; float ga = garea[i];
            unsigned long long bk = KMAX;
#pragma unroll
            for (int k = 0; k < 4; k++) {
                if (k < nk && !((usedmask >> k) & 1)) {
                    int j = tid + HT * k;
                    float r = muv + costf(c_p[k], c_b[k], c_a[k], g, ga) - v_reg[k];
                    if (r < spc_reg[k]) { spc_reg[k] = r; path[j] = (short)i; }
                    bk = umin64(bk, fkey(spc_reg[k], j));
                }
            }
#pragma unroll
            for (int off = 16; off > 0; off >>= 1)
                bk = umin64(bk, __shfl_xor_sync(FULLM, bk, off));
            if (lane == 0) sl1[par][wid] = bk;
            __syncthreads();
            unsigned long long K = sl1[par][0];
#pragma unroll
            for (int k = 1; k < NW; k++) K = umin64(K, sl1[par][k]);
            minVal = kval(K);
            int j1 = kidx(K);
            if ((j1 & (HT - 1)) == tid) usedmask |= 1 << (j1 >> 8);   // owner reg
            par ^= 1;
            int nr = row4col[j1];     // row4col constant during pop loop
            if (nr < 0) { sink = j1; break; }
            i = nr;
        }
        __syncthreads();

        // dual updates (owner regs; distinct rows per used column -> race-free)
#pragma unroll
        for (int k = 0; k < 4; k++) {
            if (k < nk && ((usedmask >> k) & 1)) {
                int j = tid + HT * k;
                float d = minVal - spc_reg[k];
                int r = row4col[j];
                if (r >= 0) u_sh[r] += d;
                v_reg[k] -= d;
            }
        }
        __syncthreads();
        if (tid == 0) {
            u_sh[cur] += minVal;
            int j = sink;
            while (true) {
                int i2 = path[j];
                row4col[j] = (short)i2;
                int tcol = col4row[i2];
                col4row[i2] = (short)j;
                j = tcol;
                if (i2 == cur) break;
            }
        }
        // reset owner-private search state
        usedmask = 0;
#pragma unroll
        for (int k = 0; k < 4; k++) spc_reg[k] = FINF;
        __syncthreads();
    }

    // ---- fused per-batch losses (fp64) ----
    double cls = 0.0, bbox = 0.0, gio = 0.0;
    for (int q = tid; q < Q; q += HT) {
        float l0 = pl[((size_t)b * Q + q) * 2 + 0];
        float l1 = pl[((size_t)b * Q + q) * 2 + 1];
        float mx = fmaxf(l0, l1);
        float lse = mx + logf(expf(l0 - mx) + expf(l1 - mx));
        cls += 0.1 * (double)(lse - l1);
    }
    if (tid < G) {
        int g = tid;
        int q = col4row[g];
        float4 mg = gt4s[g];
        float4 mp = pbox4[q];
        bbox = (double)(fabsf(mp.x - mg.x) + fabsf(mp.y - mg.y) +
                        fabsf(mp.z - mg.z) + fabsf(mp.w - mg.w));
        gio = 1.0 - (double)giou_ok(mp.x, mp.y, mp.z, mp.w, mg.x, mg.y, mg.z, mg.w);
        float l0 = pl[((size_t)b * Q + q) * 2 + 0];
        float l1 = pl[((size_t)b * Q + q) * 2 + 1];
        float mx = fmaxf(l0, l1);
        float lse = mx + logf(expf(l0 - mx) + expf(l1 - mx));
        cls += (double)(lse - l0) - 0.1 * (double)(lse - l1);
    }
#pragma unroll
    for (int off = 16; off > 0; off >>= 1) {
        cls  += __shfl_down_sync(FULLM, cls, off);
        bbox += __shfl_down_sync(FULLM, bbox, off);
        gio  += __shfl_down_sync(FULLM, gio, off);
    }
    if (lane == 0) { wsum[wid][0] = cls; wsum[wid][1] = bbox; wsum[wid][2] = gio; }
    __syncthreads();

    if (tid == 0) {
        double cls_t = 0.0, bbox_t = 0.0, gio_t = 0.0;
        for (int w = 0; w < NW; w++) {
            cls_t += wsum[w][0]; bbox_t += wsum[w][1]; gio_t += wsum[w][2];
        }
        g_part[b * 3 + 0] = cls_t;
        g_part[b * 3 + 1] = bbox_t;
        g_part[b * 3 + 2] = gio_t;
        __threadfence();
        int prev = atomicAdd(&g_done, 1);
        if (prev == B - 1) {
            g_done = 0;
            __threadfence();
            double csum = 0.0, bsum = 0.0, gsum = 0.0;
            for (int k = 0; k < B; k++) {
                csum += g_part[k * 3 + 0];
                bsum += g_part[k * 3 + 1];
                gsum += g_part[k * 3 + 2];
            }
            const double wt_sum = 64.0 + (double)(Q - G) * 0.1;  // 157.6
            double lc = (csum / wt_sum) / (double)B;
            double nb = (double)(B * G);
            double lb = bsum / nb;
            double lg = gsum / nb;
            out[0] = (float)(1.0 * lc + 5.0 * lb + 2.0 * lg);
            out[1] = (float)lc;
            out[2] = (float)lb;
            out[3] = (float)lg;
        }
    }
}

// ---------------------------------------------------------------------------
extern "C" void kernel_launch(void* const* d_in, const int* in_sizes, int n_in,
                              void* d_out, int out_size) {
    const float* pred_boxes  = (const float*)d_in[0];  // [32,1000,4]
    const float* pred_logits = (const float*)d_in[1];  // [32,1000,2]
    const float* gt_boxes    = (const float*)d_in[2];  // [32,64,4]
    float* out = (float*)d_out;

    match_kernel<<<B, HT>>>(pred_boxes, pred_logits, gt_boxes, out);
}

// round 13
// speedup vs baseline: 1.3560x; 1.0269x over previous
#include <cuda_runtime.h>
#include <math.h>
#include <float.h>

#define B 32
#define Q 1000
#define G 64
#define HT 256
#define NW (HT / 32)
#define FR_CAP 256
#define FULLM 0xffffffffu
#define KMAX 0xFFFFFFFFFFFFFFFFull

__device__ double g_part[B * 3];   // per-batch {cls, bbox, giou}
__device__ int    g_done = 0;

// ---- orderable (float,idx) packing: min(key) == (min value, then min idx) ----
__device__ __forceinline__ unsigned long long fkey(float f, int j) {
    unsigned u = __float_as_uint(f);
    u = (u & 0x80000000u) ? ~u : (u | 0x80000000u);
    return ((unsigned long long)u << 32) | (unsigned)j;
}
__device__ __forceinline__ float kval(unsigned long long k) {
    unsigned u = (unsigned)(k >> 32);
    u = (u & 0x80000000u) ? (u & 0x7fffffffu) : ~u;
    return __uint_as_float(u);
}
__device__ __forceinline__ int kidx(unsigned long long k) { return (int)(k & 0xffffffffu); }
__device__ __forceinline__ unsigned long long umin64(unsigned long long a, unsigned long long b) { return a < b ? a : b; }
__device__ __forceinline__ unsigned long long umax64(unsigned long long a, unsigned long long b) { return a > b ? a : b; }

// precise giou for the loss (matches reference math)
__device__ __forceinline__ float giou_ok(float ax1, float ay1, float ax2, float ay2,
                                         float bx1, float by1, float bx2, float by2) {
    float ix1 = fmaxf(ax1, bx1), iy1 = fmaxf(ay1, by1);
    float ix2 = fminf(ax2, bx2), iy2 = fminf(ay2, by2);
    float inter  = fmaxf(ix2 - ix1, 0.f) * fmaxf(iy2 - iy1, 0.f);
    float area_a = fmaxf(ax2 - ax1, 0.f) * fmaxf(ay2 - ay1, 0.f);
    float area_b = fmaxf(bx2 - bx1, 0.f) * fmaxf(by2 - by1, 0.f);
    float uni = area_a + area_b - inter + 1e-6f;
    float iou = inter / uni;
    float ex1 = fminf(ax1, bx1), ey1 = fminf(ay1, by1);
    float ex2 = fmaxf(ax2, bx2), ey2 = fmaxf(ay2, by2);
    float enc = fmaxf(fmaxf(ex2 - ex1, 0.f) * fmaxf(ey2 - ey1, 0.f), 1e-6f);
    return iou - (enc - uni) / enc;
}

// matching cost, single-division form:
//   giou = inter/uni - (enc-uni)/enc = (inter*enc + uni*uni)/(uni*enc) - 1
//   cost = (base+2) + 5*L1 - 2*ratio,   ratio = (inter*enc + uni^2)/(uni*enc)
// base2 = -prob0 + 2 (per column), gae = garea + 1e-6 (per row).
__device__ __forceinline__ float costf(float4 p, float base2, float ap,
                                       float4 g, float gae) {
    float dx = fminf(p.z, g.z) - fmaxf(p.x, g.x);
    float dy = fminf(p.w, g.w) - fmaxf(p.y, g.y);
    float inter = fmaxf(dx, 0.f) * fmaxf(dy, 0.f);
    float uni = (ap + gae) - inter;
    float ex = fmaxf(p.z, g.z) - fminf(p.x, g.x);
    float ey = fmaxf(p.w, g.w) - fminf(p.y, g.y);
    float enc = fmaxf(fmaxf(ex, 0.f) * fmaxf(ey, 0.f), 1e-6f);
    float ratio = __fdividef(fmaf(uni, uni, inter * enc), uni * enc);
    float l1c = fabsf(p.x - g.x) + fabsf(p.y - g.y) +
                fabsf(p.z - g.z) + fabsf(p.w - g.w);
    return fmaf(-2.f, ratio, fmaf(5.f, l1c, base2));
}

// ---------------------------------------------------------------------------
__global__ void __launch_bounds__(HT, 1) match_kernel(
        const float* __restrict__ pb, const float* __restrict__ pl,
        const float* __restrict__ gb, float* __restrict__ out) {
    const int b = blockIdx.x;
    const int tid = threadIdx.x;
    const int lane = tid & 31, wid = tid >> 5;
    const float FINF = FLT_MAX;

    __shared__ float4 pbox4[Q];
    __shared__ float2 baux[Q];          // (base2 = 2-prob0, area_p)
    __shared__ float4 gt4s[G];
    __shared__ float  gae_s[G];         // garea + 1e-6
    __shared__ float  u_sh[G];
    __shared__ short  path[Q];
    __shared__ short  row4col[Q];
    __shared__ short  col4row[G];
    __shared__ float  umin[G];
    __shared__ int    uarg[G];
    __shared__ short  freerows[FR_CAP];
    __shared__ unsigned long long sl1[2][NW], sl2[2][NW];
    __shared__ double wsum[NW][3];
    __shared__ int    nfree_sh;

    // ---- load inputs ----
    for (int j = tid; j < Q; j += HT) {
        float4 p = *reinterpret_cast<const float4*>(pb + ((size_t)b * Q + j) * 4);
        pbox4[j] = p;
        float l0 = pl[((size_t)b * Q + j) * 2 + 0];
        float l1 = pl[((size_t)b * Q + j) * 2 + 1];
        float base = -1.0f / (1.0f + __expf(l1 - l0));
        float ap = fmaxf(p.z - p.x, 0.f) * fmaxf(p.w - p.y, 0.f);
        baux[j] = make_float2(base + 2.0f, ap);
        row4col[j] = -1;
    }
    if (tid < G) {
        float4 g = *reinterpret_cast<const float4*>(gb + ((size_t)b * G + tid) * 4);
        gt4s[tid] = g;
        gae_s[tid] = fmaxf(g.z - g.x, 0.f) * fmaxf(g.w - g.y, 0.f) + 1e-6f;
    }
    __syncthreads();

    // ---- register-cache this thread's 4 owned columns (j = tid + 256k) ----
    const int nk = (tid < Q - 3 * HT) ? 4 : 3;     // k=3 valid iff tid < 232
    float4 c_p[4]; float c_b[4], c_a[4], v_reg[4], spc_reg[4];
    int usedmask = 0;
#pragma unroll
    for (int k = 0; k < 4; k++) {
        int j = tid + HT * k;
        if (j < Q) {
            c_p[k] = pbox4[j];
            float2 ba = baux[j];
            c_b[k] = ba.x; c_a[k] = ba.y;
        }
        v_reg[k] = 0.f; spc_reg[k] = FINF;
    }

    // ---- P1: row minima, warp-per-row ----
    for (int r = wid; r < G; r += NW) {
        float4 g = gt4s[r]; float gae = gae_s[r];
        float best = FINF; int bj = Q;
        for (int j = lane; j < Q; j += 32) {
            float2 ba = baux[j];
            float c = costf(pbox4[j], ba.x, ba.y, g, gae);
            if (c < best) { best = c; bj = j; }
        }
#pragma unroll
        for (int off = 16; off > 0; off >>= 1) {
            float om = __shfl_down_sync(FULLM, best, off);
            int   oj = __shfl_down_sync(FULLM, bj, off);
            if (om < best || (om == best && oj < bj)) { best = om; bj = oj; }
        }
        if (lane == 0) { umin[r] = best; uarg[r] = bj; }
    }
    __syncthreads();
    if (tid < G) u_sh[tid] = umin[tid];
    // ---- P2: greedy tight-edge assignment ----
    if (tid == 0) {
        int nf = 0;
        for (int r = 0; r < G; r++) {
            int j = uarg[r];
            if (row4col[j] < 0) { row4col[j] = (short)r; col4row[r] = (short)j; }
            else { col4row[r] = -1; freerows[nf++] = (short)r; }
        }
        nfree_sh = nf;
    }
    __syncthreads();

    // ---- P3: augmenting row reduction (packed keys, reg v) ----
    {
        int idx = 0, cnt = nfree_sh, iters = 0, par = 0;
        while (idx < cnt && iters < 192) {
            iters++;
            int i = freerows[idx]; idx++;
            float4 g = gt4s[i]; float gae = gae_s[i];
            unsigned long long k1 = KMAX, k2 = KMAX;
#pragma unroll
            for (int k = 0; k < 4; k++) {
                if (k < nk) {
                    int j = tid + HT * k;
                    float red = costf(c_p[k], c_b[k], c_a[k], g, gae) - v_reg[k];
                    unsigned long long kk = fkey(red, j);
                    if (kk < k1) { k2 = k1; k1 = kk; }
                    else if (kk < k2) { k2 = kk; }
                }
            }
#pragma unroll
            for (int off = 16; off > 0; off >>= 1) {
                unsigned long long o1 = __shfl_xor_sync(FULLM, k1, off);
                unsigned long long o2 = __shfl_xor_sync(FULLM, k2, off);
                unsigned long long mx = umax64(k1, o1);
                k1 = umin64(k1, o1);
                k2 = umin64(mx, umin64(k2, o2));
            }
            if (lane == 0) { sl1[par][wid] = k1; sl2[par][wid] = k2; }
            __syncthreads();
            unsigned long long K1 = sl1[par][0], K2 = sl2[par][0];
#pragma unroll
            for (int k = 1; k < NW; k++) {
                unsigned long long o1 = sl1[par][k], o2 = sl2[par][k];
                unsigned long long mx = umax64(K1, o1);
                K1 = umin64(K1, o1);
                K2 = umin64(mx, umin64(K2, o2));
            }
            float m1 = kval(K1), m2 = kval(K2);
            int j1 = kidx(K1), j2 = kidx(K2);
            // decision (ALL threads read row4col BEFORE tid0 writes it)
            bool strict = (m1 < m2);
            int jt = j1;
            int i0 = row4col[jt];
            if (!strict && i0 >= 0 && j2 < Q) { jt = j2; i0 = row4col[jt]; }
            __syncthreads();   // order decision-reads before tid0's writes
            if (i0 >= 0) {
                if (strict) idx--;
                else if (cnt < FR_CAP) cnt++;
            }
            // v update: owner applies the (identically computed) delta
            if (strict && ((jt & (HT - 1)) == tid)) v_reg[jt >> 8] -= (m2 - m1);
            if (tid == 0) {
                u_sh[i] = m2;
                row4col[jt] = (short)i; col4row[i] = (short)jt;
                if (i0 >= 0) {
                    col4row[i0] = -1;
                    if (strict) freerows[idx] = (short)i0;
                    else if (cnt - 1 < FR_CAP) freerows[cnt - 1] = (short)i0;
                }
            }
            par ^= 1;
            __syncthreads();
        }
    }

    // ---- P4: SAP (reg spc/used/v; one barrier per pop) ----
    for (int cur = 0; cur < G; cur++) {
        if (col4row[cur] >= 0) continue;

        int i = cur, par = 0, sink = -1;
        float minVal = 0.f;

        while (true) {
            float muv = minVal - u_sh[i];
            float4 g = gt4s[i]; float gae = gae_s[i];
            float best = FINF; int bestj = 0x7FFFFFFF;
#pragma unroll
            for (int k = 0; k < 4; k++) {
                if (k < nk && !((usedmask >> k) & 1)) {
                    int j = tid + HT * k;
                    float r = muv + costf(c_p[k], c_b[k], c_a[k], g, gae) - v_reg[k];
                    float s = spc_reg[k];
                    if (r < s) { s = r; spc_reg[k] = r; path[j] = (short)i; }
                    if (s < best) { best = s; bestj = j; }   // ascending k => min j kept
                }
            }
            unsigned long long bk = (bestj <= Q) ? fkey(best, bestj) : KMAX;
#pragma unroll
            for (int off = 16; off > 0; off >>= 1)
                bk = umin64(bk, __shfl_xor_sync(FULLM, bk, off));
            if (lane == 0) sl1[par][wid] = bk;
            __syncthreads();
            unsigned long long K = sl1[par][0];
#pragma unroll
            for (int k = 1; k < NW; k++) K = umin64(K, sl1[par][k]);
            minVal = kval(K);
            int j1 = kidx(K);
            if ((j1 & (HT - 1)) == tid) usedmask |= 1 << (j1 >> 8);   // owner reg
            par ^= 1;
            int nr = row4col[j1];     // row4col constant during pop loop
            if (nr < 0) { sink = j1; break; }
            i = nr;
        }
        __syncthreads();

        // dual updates (owner regs; distinct rows per used column -> race-free)
#pragma unroll
        for (int k = 0; k < 4; k++) {
            if (k < nk && ((usedmask >> k) & 1)) {
                int j = tid + HT * k;
                float d = minVal - spc_reg[k];
                int r = row4col[j];
                if (r >= 0) u_sh[r] += d;
                v_reg[k] -= d;
            }
        }
        __syncthreads();
        if (tid == 0) {
            u_sh[cur] += minVal;
            int j = sink;
            while (true) {
                int i2 = path[j];
                row4col[j] = (short)i2;
                int tcol = col4row[i2];
                col4row[i2] = (short)j;
                j = tcol;
                if (i2 == cur) break;
            }
        }
        // reset owner-private search state
        usedmask = 0;
#pragma unroll
        for (int k = 0; k < 4; k++) spc_reg[k] = FINF;
        __syncthreads();
    }

    // ---- fused per-batch losses (fp64) ----
    double cls = 0.0, bbox = 0.0, gio = 0.0;
    for (int q = tid; q < Q; q += HT) {
        float l0 = pl[((size_t)b * Q + q) * 2 + 0];
        float l1 = pl[((size_t)b * Q + q) * 2 + 1];
        float mx = fmaxf(l0, l1);
        float lse = mx + logf(expf(l0 - mx) + expf(l1 - mx));
        cls += 0.1 * (double)(lse - l1);
    }
    if (tid < G) {
        int g = tid;
        int q = col4row[g];
        float4 mg = gt4s[g];
        float4 mp = pbox4[q];
        bbox = (double)(fabsf(mp.x - mg.x) + fabsf(mp.y - mg.y) +
                        fabsf(mp.z - mg.z) + fabsf(mp.w - mg.w));
        gio = 1.0 - (double)giou_ok(mp.x, mp.y, mp.z, mp.w, mg.x, mg.y, mg.z, mg.w);
        float l0 = pl[((size_t)b * Q + q) * 2 + 0];
        float l1 = pl[((size_t)b * Q + q) * 2 + 1];
        float mx = fmaxf(l0, l1);
        float lse = mx + logf(expf(l0 - mx) + expf(l1 - mx));
        cls += (double)(lse - l0) - 0.1 * (double)(lse - l1);
    }
#pragma unroll
    for (int off = 16; off > 0; off >>= 1) {
        cls  += __shfl_down_sync(FULLM, cls, off);
        bbox += __shfl_down_sync(FULLM, bbox, off);
        gio  += __shfl_down_sync(FULLM, gio, off);
    }
    if (lane == 0) { wsum[wid][0] = cls; wsum[wid][1] = bbox; wsum[wid][2] = gio; }
    __syncthreads();

    if (tid == 0) {
        double cls_t = 0.0, bbox_t = 0.0, gio_t = 0.0;
        for (int w = 0; w < NW; w++) {
            cls_t += wsum[w][0]; bbox_t += wsum[w][1]; gio_t += wsum[w][2];
        }
        g_part[b * 3 + 0] = cls_t;
        g_part[b * 3 + 1] = bbox_t;
        g_part[b * 3 + 2] = gio_t;
        __threadfence();
        int prev = atomicAdd(&g_done, 1);
        if (prev == B - 1) {
            g_done = 0;
            __threadfence();
            double csum = 0.0, bsum = 0.0, gsum = 0.0;
            for (int k = 0; k < B; k++) {
                csum += g_part[k * 3 + 0];
                bsum += g_part[k * 3 + 1];
                gsum += g_part[k * 3 + 2];
            }
            const double wt_sum = 64.0 + (double)(Q - G) * 0.1;  // 157.6
            double lc = (csum / wt_sum) / (double)B;
            double nb = (double)(B * G);
            double lb = bsum / nb;
            double lg = gsum / nb;
            out[0] = (float)(1.0 * lc + 5.0 * lb + 2.0 * lg);
            out[1] = (float)lc;
            out[2] = (float)lb;
            out[3] = (float)lg;
        }
    }
}

// ---------------------------------------------------------------------------
extern "C" void kernel_launch(void* const* d_in, const int* in_sizes, int n_in,
                              void* d_out, int out_size) {
    const float* pred_boxes  = (const float*)d_in[0];  // [32,1000,4]
    const float* pred_logits = (const float*)d_in[1];  // [32,1000,2]
    const float* gt_boxes    = (const float*)d_in[2];  // [32,64,4]
    float* out = (float*)d_out;

    match_kernel<<<B, HT>>>(pred_boxes, pred_logits, gt_boxes, out);
}